// round 17
// baseline (speedup 1.0000x reference)
#include <cuda_runtime.h>
#include <cuda_fp16.h>
#include <stdint.h>

#define NODES 50000
#define EDGES 800000
#define DD    128
#define EPS   1e-5f

// ---------------- scratch (static device globals; no allocation) ----------------
__device__ __half g_aggh[(size_t)NODES * DD]; // fp16 agg (gather output, GEMM input)
__device__ float  g_h1[(size_t)NODES * DD];   // pre-BN layer output (f32, for stats/BN)
__device__ __half g_hh[(size_t)NODES * DD];   // fp16 shadow of current h
__device__ __half g_wh[6 * DD * DD];          // fp16 weights TRANSPOSED [n][k]: [l]=self, [3+l]=neigh
__device__ float  g_rdeg[NODES];
__device__ int    g_deg[NODES];
__device__ int    g_csr_ptr[NODES + 1];
__device__ int    g_cursor[NODES];
__device__ int    g_csr_src[EDGES];
__device__ int    g_bsum[256];
__device__ float  g_stats[2 * DD];

// ---------------- degree + CSR build ----------------
__global__ void k_count_deg(const int* __restrict__ dst, int e) {
    int i = blockIdx.x * blockDim.x + threadIdx.x;
    if (i < e) atomicAdd(&g_deg[dst[i]], 1);
}

__global__ void k_scan1(int n) {
    __shared__ int s[256];
    int tid = threadIdx.x;
    int i = blockIdx.x * 256 + tid;
    int v = (i < n) ? g_deg[i] : 0;
    s[tid] = v;
    __syncthreads();
#pragma unroll
    for (int o = 1; o < 256; o <<= 1) {
        int x = (tid >= o) ? s[tid - o] : 0;
        __syncthreads();
        s[tid] += x;
        __syncthreads();
    }
    if (i < n) g_csr_ptr[i] = s[tid] - v;   // block-local exclusive
    if (tid == 255) g_bsum[blockIdx.x] = s[255];
}

// scan3 with inline block-offset reduction
__global__ void k_scan3(int n, int e) {
    __shared__ int s[256];
    int tid = threadIdx.x;
    int partial = 0;
    for (int j = tid; j < blockIdx.x; j += 256) partial += g_bsum[j];
    s[tid] = partial;
    __syncthreads();
#pragma unroll
    for (int o = 128; o > 0; o >>= 1) {
        if (tid < o) s[tid] += s[tid + o];
        __syncthreads();
    }
    int boff = s[0];
    int i = blockIdx.x * 256 + tid;
    if (i < n) {
        int p = g_csr_ptr[i] + boff;
        g_csr_ptr[i] = p;
        g_cursor[i] = p;
        int d = g_deg[i];
        g_rdeg[i] = 1.0f / (float)(d > 0 ? d : 1);
    }
    if (i == 0) g_csr_ptr[n] = e;
}

__global__ void k_fill(const int* __restrict__ src, const int* __restrict__ dst, int e) {
    int i = blockIdx.x * blockDim.x + threadIdx.x;
    if (i < e) {
        int pos = atomicAdd(&g_cursor[dst[i]], 1);
        g_csr_src[pos] = src[i];
    }
}

// ------- fp16 shadows: feat (direct) + weights (TRANSPOSED to [n][k]) -------------
__global__ void k_tohalf_all(const float* __restrict__ feat,
                             const float* __restrict__ Wself,
                             const float* __restrict__ Wneigh,
                             int feat4, int w4) {   // counts in float4 units
    int idx = blockIdx.x * blockDim.x + threadIdx.x;
    if (idx < feat4) {
        float4 v = reinterpret_cast<const float4*>(feat)[idx];
        __half2 lo = __floats2half2_rn(v.x, v.y);
        __half2 hi = __floats2half2_rn(v.z, v.w);
        uint2 u;
        u.x = *reinterpret_cast<uint32_t*>(&lo);
        u.y = *reinterpret_cast<uint32_t*>(&hi);
        reinterpret_cast<uint2*>(g_hh)[idx] = u;
    } else if (idx < feat4 + 2 * w4) {
        int k4 = idx - feat4;
        const float* srcp = (k4 < w4) ? Wself : Wneigh;
        int j = (k4 < w4) ? k4 : k4 - w4;            // float4 index within 3*DD*DD tensor
        __half* dstp = g_wh + ((k4 < w4) ? 0 : 3 * DD * DD);
        int l  = j / (DD * DD / 4);
        int r  = j % (DD * DD / 4);
        int kk = r / (DD / 4);                       // source row (k)
        int n0 = (r % (DD / 4)) * 4;                 // source col base (n)
        float4 v = reinterpret_cast<const float4*>(srcp)[j];
        __half* base = dstp + (size_t)l * DD * DD;
        base[(n0 + 0) * DD + kk] = __float2half_rn(v.x);
        base[(n0 + 1) * DD + kk] = __float2half_rn(v.y);
        base[(n0 + 2) * DD + kk] = __float2half_rn(v.z);
        base[(n0 + 3) * DD + kk] = __float2half_rn(v.w);
    }
}

// ------ gather: 16 lanes per dst node (2 nodes/warp), uint4 rows, fp16 agg out -----
__global__ __launch_bounds__(256)
void k_gather(int n) {
    int node   = (blockIdx.x * blockDim.x + threadIdx.x) >> 4;
    int lane16 = threadIdx.x & 15;
    if (node >= n) return;
    const __half* hh = g_hh;
    int beg = g_csr_ptr[node];
    int end = g_csr_ptr[node + 1];
    float4 acc0 = make_float4(0.f, 0.f, 0.f, 0.f);
    float4 acc1 = make_float4(0.f, 0.f, 0.f, 0.f);
    for (int base = beg; base < end; base += 16) {
        int mye  = base + lane16;
        int sidx = (mye < end) ? g_csr_src[mye] : 0;
        int cnt  = min(16, end - base);
        int j = 0;
        for (; j + 7 < cnt; j += 8) {
            int  ss[8];
            uint4 uu[8];
#pragma unroll
            for (int q = 0; q < 8; q++)
                ss[q] = __shfl_sync(0xffffffffu, sidx, j + q, 16);
#pragma unroll
            for (int q = 0; q < 8; q++)
                uu[q] = *reinterpret_cast<const uint4*>(hh + (size_t)ss[q] * DD + lane16 * 8);
#pragma unroll
            for (int q = 0; q < 8; q++) {
                float2 a = __half22float2(*reinterpret_cast<__half2*>(&uu[q].x));
                float2 b = __half22float2(*reinterpret_cast<__half2*>(&uu[q].y));
                float2 c = __half22float2(*reinterpret_cast<__half2*>(&uu[q].z));
                float2 d = __half22float2(*reinterpret_cast<__half2*>(&uu[q].w));
                acc0.x += a.x; acc0.y += a.y; acc0.z += b.x; acc0.w += b.y;
                acc1.x += c.x; acc1.y += c.y; acc1.z += d.x; acc1.w += d.y;
            }
        }
        for (; j < cnt; j++) {
            int s0 = __shfl_sync(0xffffffffu, sidx, j, 16);
            uint4 u0 = *reinterpret_cast<const uint4*>(hh + (size_t)s0 * DD + lane16 * 8);
            float2 a = __half22float2(*reinterpret_cast<__half2*>(&u0.x));
            float2 b = __half22float2(*reinterpret_cast<__half2*>(&u0.y));
            float2 c = __half22float2(*reinterpret_cast<__half2*>(&u0.z));
            float2 d = __half22float2(*reinterpret_cast<__half2*>(&u0.w));
            acc0.x += a.x; acc0.y += a.y; acc0.z += b.x; acc0.w += b.y;
            acc1.x += c.x; acc1.y += c.y; acc1.z += d.x; acc1.w += d.y;
        }
    }
    float rd = g_rdeg[node];
    __half2 p0 = __floats2half2_rn(acc0.x * rd, acc0.y * rd);
    __half2 p1 = __floats2half2_rn(acc0.z * rd, acc0.w * rd);
    __half2 p2 = __floats2half2_rn(acc1.x * rd, acc1.y * rd);
    __half2 p3 = __floats2half2_rn(acc1.z * rd, acc1.w * rd);
    uint4 u;
    u.x = *reinterpret_cast<uint32_t*>(&p0);
    u.y = *reinterpret_cast<uint32_t*>(&p1);
    u.z = *reinterpret_cast<uint32_t*>(&p2);
    u.w = *reinterpret_cast<uint32_t*>(&p3);
    *reinterpret_cast<uint4*>(g_aggh + (size_t)node * DD + lane16 * 8) = u;
}

// ---------------- fp16 tensor-core dual GEMM + bias + residual(fp16) --------------
__device__ __forceinline__ void mma_f16(float* d, const uint32_t* a, const uint32_t* b) {
    asm volatile(
        "mma.sync.aligned.m16n8k16.row.col.f32.f16.f16.f32 "
        "{%0,%1,%2,%3}, {%4,%5,%6,%7}, {%8,%9}, {%0,%1,%2,%3};\n"
        : "+f"(d[0]), "+f"(d[1]), "+f"(d[2]), "+f"(d[3])
        : "r"(a[0]), "r"(a[1]), "r"(a[2]), "r"(a[3]), "r"(b[0]), "r"(b[1]));
}

#define BM 128
#define BK 16
#define T_STRIDE 10   // 8 half2-words per row + 2 pad

__global__ __launch_bounds__(256, 2)
void k_gemm_tc(const __half* __restrict__ Wsh, const __half* __restrict__ Wnh,
               const float* __restrict__ bias, float* __restrict__ out, int nrows) {
    __shared__ uint32_t Ah[128][T_STRIDE];
    __shared__ uint32_t Aa[128][T_STRIDE];
    __shared__ uint32_t Bs[128][T_STRIDE];
    __shared__ uint32_t Bn[128][T_STRIDE];

    const int tid  = threadIdx.x;
    const int warp = tid >> 5;
    const int lane = tid & 31;
    const int g    = lane >> 2;
    const int t    = lane & 3;
    const int wm   = warp & 3;
    const int wn   = warp >> 2;
    const int m0   = blockIdx.x * BM;
    const int wrow = wm * 32;
    const int wcol = wn * 64;

    float acc[2][8][4];
#pragma unroll
    for (int mt = 0; mt < 2; mt++)
#pragma unroll
        for (int nt = 0; nt < 8; nt++)
#pragma unroll
            for (int j = 0; j < 4; j++) acc[mt][nt][j] = 0.f;

    for (int kc = 0; kc < DD / BK; kc++) {
        const int ks = kc * BK;
#pragma unroll
        for (int r = 0; r < 2; r++) {
            int id  = tid + r * 256;          // 0..511
            int row = id >> 2;                // 0..127
            int q   = id & 3;                 // 0..3 (uint2 within row)
            int grow = m0 + row;
            uint2 uh = make_uint2(0u, 0u);
            uint2 ua = make_uint2(0u, 0u);
            if (grow < nrows) {
                size_t off = (size_t)grow * DD + ks + q * 4;
                uh = *reinterpret_cast<const uint2*>(g_hh + off);
                ua = *reinterpret_cast<const uint2*>(g_aggh + off);
            }
            *reinterpret_cast<uint2*>(&Ah[row][q * 2]) = uh;
            *reinterpret_cast<uint2*>(&Aa[row][q * 2]) = ua;
        }
#pragma unroll
        for (int r = 0; r < 2; r++) {
            int id  = tid + r * 256;
            int row = id >> 2;                // n
            int q   = id & 3;
            size_t off = (size_t)row * DD + ks + q * 4;
            uint2 us = *reinterpret_cast<const uint2*>(Wsh + off);
            uint2 un = *reinterpret_cast<const uint2*>(Wnh + off);
            *reinterpret_cast<uint2*>(&Bs[row][q * 2]) = us;
            *reinterpret_cast<uint2*>(&Bn[row][q * 2]) = un;
        }
        __syncthreads();

        uint32_t a[2][4], b[8][2];
#pragma unroll
        for (int mt = 0; mt < 2; mt++) {
            int r = wrow + mt * 16;
            a[mt][0] = Ah[r + g][t];
            a[mt][1] = Ah[r + g + 8][t];
            a[mt][2] = Ah[r + g][t + 4];
            a[mt][3] = Ah[r + g + 8][t + 4];
        }
#pragma unroll
        for (int nt = 0; nt < 8; nt++) {
            int c = wcol + nt * 8 + g;
            b[nt][0] = Bs[c][t];
            b[nt][1] = Bs[c][t + 4];
        }
#pragma unroll
        for (int mt = 0; mt < 2; mt++)
#pragma unroll
            for (int nt = 0; nt < 8; nt++)
                mma_f16(acc[mt][nt], a[mt], b[nt]);
#pragma unroll
        for (int mt = 0; mt < 2; mt++) {
            int r = wrow + mt * 16;
            a[mt][0] = Aa[r + g][t];
            a[mt][1] = Aa[r + g + 8][t];
            a[mt][2] = Aa[r + g][t + 4];
            a[mt][3] = Aa[r + g + 8][t + 4];
        }
#pragma unroll
        for (int nt = 0; nt < 8; nt++) {
            int c = wcol + nt * 8 + g;
            b[nt][0] = Bn[c][t];
            b[nt][1] = Bn[c][t + 4];
        }
#pragma unroll
        for (int mt = 0; mt < 2; mt++)
#pragma unroll
            for (int nt = 0; nt < 8; nt++)
                mma_f16(acc[mt][nt], a[mt], b[nt]);
        __syncthreads();
    }

    // epilogue: + bias + residual (fp16 shadow), write f32 out
#pragma unroll
    for (int mt = 0; mt < 2; mt++) {
#pragma unroll
        for (int rr = 0; rr < 2; rr++) {
            int grow = m0 + wrow + mt * 16 + g + rr * 8;
            if (grow < nrows) {
#pragma unroll
                for (int nt = 0; nt < 8; nt++) {
                    int col = wcol + nt * 8 + t * 2;
                    size_t off = (size_t)grow * DD + col;
                    __half2 rh = *reinterpret_cast<const __half2*>(g_hh + off);
                    float2 res = __half22float2(rh);
                    float2 bv  = *reinterpret_cast<const float2*>(bias + col);
                    float2 o;
                    o.x = acc[mt][nt][rr * 2 + 0] + bv.x + res.x;
                    o.y = acc[mt][nt][rr * 2 + 1] + bv.y + res.y;
                    *reinterpret_cast<float2*>(out + off) = o;
                }
            }
        }
    }
}

// ---------------- column stats (sum, sumsq) ----------------
__global__ __launch_bounds__(256)
void k_stats(const float* __restrict__ x, int n) {
    __shared__ float sh[8][DD];
    __shared__ float shq[8][DD];
    int lane = threadIdx.x & 31;
    int w    = threadIdx.x >> 5;
    int c    = lane * 4;
    float4 s = make_float4(0.f, 0.f, 0.f, 0.f);
    float4 q = make_float4(0.f, 0.f, 0.f, 0.f);
    for (int r = blockIdx.x * 8 + w; r < n; r += gridDim.x * 8) {
        float4 v = *reinterpret_cast<const float4*>(x + (size_t)r * DD + c);
        s.x += v.x; s.y += v.y; s.z += v.z; s.w += v.w;
        q.x += v.x * v.x; q.y += v.y * v.y; q.z += v.z * v.z; q.w += v.w * v.w;
    }
    *reinterpret_cast<float4*>(&sh[w][c])  = s;
    *reinterpret_cast<float4*>(&shq[w][c]) = q;
    __syncthreads();
    if (threadIdx.x < DD) {
        float ss = 0.f, qq = 0.f;
#pragma unroll
        for (int r = 0; r < 8; r++) { ss += sh[r][threadIdx.x]; qq += shq[r][threadIdx.x]; }
        atomicAdd(&g_stats[threadIdx.x], ss);
        atomicAdd(&g_stats[DD + threadIdx.x], qq);
    }
}

// ---------------- BN + ReLU; emits ONLY fp16 shadow ----------------
__global__ void k_bn_relu(const float* __restrict__ hn, const float* __restrict__ gamma,
                          const float* __restrict__ beta, int n) {
    int idx   = blockIdx.x * blockDim.x + threadIdx.x;
    int total = n * (DD / 4);
    if (idx >= total) return;
    int c4 = idx & 31;
    int c  = c4 * 4;
    float inv = 1.0f / (float)n;

    float4 v = reinterpret_cast<const float4*>(hn)[idx];
    float4 o;
#define BN_ONE(comp, cc)                                            \
    {                                                               \
        float mu  = g_stats[cc] * inv;                              \
        float var = g_stats[DD + cc] * inv - mu * mu;               \
        float sc  = rsqrtf(var + EPS) * __ldg(gamma + cc);          \
        float sh  = __ldg(beta + cc) - mu * sc;                     \
        o.comp = fmaxf(fmaf(v.comp, sc, sh), 0.f);                  \
    }
    BN_ONE(x, c + 0)
    BN_ONE(y, c + 1)
    BN_ONE(z, c + 2)
    BN_ONE(w, c + 3)
#undef BN_ONE
    __half2 lo = __floats2half2_rn(o.x, o.y);
    __half2 hi = __floats2half2_rn(o.z, o.w);
    uint2 u;
    u.x = *reinterpret_cast<uint32_t*>(&lo);
    u.y = *reinterpret_cast<uint32_t*>(&hi);
    reinterpret_cast<uint2*>(g_hh)[idx] = u;
}

// ---------------- launch ----------------
extern "C" void kernel_launch(void* const* d_in, const int* in_sizes, int n_in,
                              void* d_out, int out_size) {
    const float* feat   = (const float*)d_in[0];
    const int*   src    = (const int*)d_in[1];
    const int*   dst    = (const int*)d_in[2];
    const float* Wself  = (const float*)d_in[3];
    const float* Wneigh = (const float*)d_in[4];
    const float* bias   = (const float*)d_in[5];
    const float* gamma  = (const float*)d_in[6];
    const float* beta   = (const float*)d_in[7];
    float* out = (float*)d_out;

    const int N = in_sizes[0] / DD;
    const int E = in_sizes[1];

    void *p_deg, *p_stats, *p_h1, *p_wh;
    cudaGetSymbolAddress(&p_deg, g_deg);
    cudaGetSymbolAddress(&p_stats, g_stats);
    cudaGetSymbolAddress(&p_h1, g_h1);
    cudaGetSymbolAddress(&p_wh, g_wh);
    const __half* wh = (const __half*)p_wh;

    // ---- CSR build + fp16 shadows ----
    const int nb = (N + 255) / 256;
    const int feat4 = N * (DD / 4);
    const int w4    = 3 * DD * DD / 4;
    cudaMemsetAsync(p_deg, 0, (size_t)N * sizeof(int), 0);
    k_tohalf_all<<<(feat4 + 2 * w4 + 255) / 256, 256>>>(feat, Wself, Wneigh, feat4, w4);
    k_count_deg<<<(E + 255) / 256, 256>>>(dst, E);
    k_scan1<<<nb, 256>>>(N);
    k_scan3<<<nb, 256>>>(N, E);
    k_fill<<<(E + 255) / 256, 256>>>(src, dst, E);

    const int gemm_blocks   = (N + BM - 1) / BM;
    const int gather_blocks = (N + 15) / 16;     // 16 lanes per node, 16 nodes/block
    const int bn_blocks     = (N * (DD / 4) + 255) / 256;

    for (int l = 0; l < 3; l++) {
        k_gather<<<gather_blocks, 256>>>(N);

        const __half* Wsh = wh + (size_t)l * DD * DD;
        const __half* Wnh = wh + (size_t)(3 + l) * DD * DD;
        const float*  bl  = bias + (size_t)l * DD;

        if (l < 2) {
            cudaMemsetAsync(p_stats, 0, 2 * DD * sizeof(float), 0);
            k_gemm_tc<<<gemm_blocks, 256>>>(Wsh, Wnh, bl, (float*)p_h1, N);
            k_stats<<<128, 256>>>((const float*)p_h1, N);
            k_bn_relu<<<bn_blocks, 256>>>((const float*)p_h1,
                                          gamma + (size_t)l * DD,
                                          beta + (size_t)l * DD, N);
        } else {
            k_gemm_tc<<<gemm_blocks, 256>>>(Wsh, Wnh, bl, out, N);
        }
    }
    (void)n_in; (void)out_size;
}